// round 13
// baseline (speedup 1.0000x reference)
#include <cuda_runtime.h>
typedef unsigned int u32;

#define HH 4096
#define ROWF 12288          // floats per image row
#define TPB 128             // one thread per PIXEL (all 3 channels)
#define RS 408              // floats per staged row (128+8 halo cols)
#define BUFF 1632           // floats per 4-row stage buffer
#define BUFB 6528           // bytes per 4-row stage buffer

// horizontal taps: radius-1, renormalized to unit applied mass
#define KH0 0.78698593f
#define KH1 0.10650699f
// vertical taps: radius-2, reference-normalized
#define K0f 0.78657070f
#define K1f 0.10645078f
#define K2f 2.63866e-4f
#define DECAYf 0.60653065971263342f
#define OMDf   0.39346934028736658f
#define INV3f  0.33333322222f        // 1/(3 + 1e-6)

__global__ __launch_bounds__(TPB, 4)
void chem_kernel(const float* __restrict__ D, const float* __restrict__ Cm,
                 float* __restrict__ out)
{
    __shared__ float stage[4 * BUFF];    // 26112 B, 4-deep 4-row ring

    const int tid = threadIdx.x;         // pixel within strip
    const int w0  = blockIdx.x << 7;     // 32 strips of 128 cols
    const int h0  = blockIdx.y << 8;     // 16 chunks of 256 rows

    float cm[9];
#pragma unroll
    for (int i = 0; i < 9; ++i) cm[i] = __ldg(Cm + i);

    // cp.async loader: 408 float4 per 4-row batch -> 4 mappings/thread
    int  jm[4]; long gm[4]; bool okm[4]; u32 sa[4];
    const u32 sb0 = (u32)__cvta_generic_to_shared(stage);
#pragma unroll
    for (int m = 0; m < 4; ++m) {
        const int idx = tid + m * TPB;
        const int j = idx / 102, v = idx - 102 * j;
        jm[m] = j;
        const long g = (long)(w0 - 4) * 3 + 4 * v;
        gm[m] = g;
        okm[m] = (idx < 408) && (g >= 0) && (g + 4 <= ROWF);
        sa[m] = sb0 + (u32)((j * RS + 4 * v) * 4);
    }

    float hbr[3][8];                     // horizontal-blur rings
#pragma unroll
    for (int c = 0; c < 3; ++c)
#pragma unroll
        for (int k = 0; k < 8; ++k) hbr[c][k] = 0.f;
    float dRr[3][4], sRr[3][4];          // lag-2 density / soft rings
    float s3[3] = {0.f, 0.f, 0.f};       // IIR states

    int rb = h0 - 30;                    // 72 batches of 4 rows; emit from k=8
    float* opt = out + (long)h0 * ROWF + (w0 + tid) * 3;

// mapping 3 covers vec idx >= 384 only for tid < 24; the instruction itself
// must be predicated (src-size-0 still zero-fills its smem destination).
#define CPA(M, RB, SB) { \
    const int row = (RB) + jm[M]; \
    const int sz  = (okm[M] && row >= 0 && row < HH) ? 16 : 0; \
    const float* gp = sz ? (D + (long)row * ROWF + gm[M]) : D; \
    asm volatile("cp.async.cg.shared.global [%0], [%1], 16, %2;\n" \
                 :: "r"(sa[M] + (u32)(SB) * BUFB), "l"(gp), "r"(sz) : "memory"); }

#define ISSUE(RB, SB) { \
    CPA(0, RB, SB) CPA(1, RB, SB) CPA(2, RB, SB) \
    if (tid < 24) CPA(3, RB, SB) \
    asm volatile("cp.async.commit_group;\n" ::: "memory"); }

// Row at phase S (= 4k+J, so S&3 == J). Output row ro = r-2 (lag-2 rings).
// 9 contiguous stage floats: cols p-1,p,p+1 x ch0..2. Conflict-free LDS.
#define ROWB(S, J, EMIT) { \
    const float xa0 = bps[(J)*RS+ 9], xa1 = bps[(J)*RS+10], xa2 = bps[(J)*RS+11]; \
    const float xb0 = bps[(J)*RS+12], xb1 = bps[(J)*RS+13], xb2 = bps[(J)*RS+14]; \
    const float xc0 = bps[(J)*RS+15], xc1 = bps[(J)*RS+16], xc2 = bps[(J)*RS+17]; \
    s3[0] = fmaf(DECAYf, s3[0], xb0); \
    s3[1] = fmaf(DECAYf, s3[1], xb1); \
    s3[2] = fmaf(DECAYf, s3[2], xb2); \
    hbr[0][(S)&7] = fmaf(xa0 + xc0, KH1, xb0 * KH0); \
    hbr[1][(S)&7] = fmaf(xa1 + xc1, KH1, xb1 * KH0); \
    hbr[2][(S)&7] = fmaf(xa2 + xc2, KH1, xb2 * KH0); \
    if (EMIT) { \
        float vb[3], ih[3], dd[3]; \
        _Pragma("unroll") \
        for (int c = 0; c < 3; ++c) { \
            float v_ = hbr[c][((S)+6)&7] * K0f; \
            v_ = fmaf(hbr[c][((S)+5)&7] + hbr[c][((S)+7)&7], K1f, v_); \
            v_ = fmaf(hbr[c][((S)+4)&7] + hbr[c][(S)&7],     K2f, v_); \
            vb[c] = v_; \
            dd[c] = dRr[c][((J)+2)&3]; \
            const float s_ = sRr[c][((J)+2)&3]; \
            ih[c] = s_ + (dd[c] * INV3f) * (v_ - s_); \
        } \
        _Pragma("unroll") \
        for (int j = 0; j < 3; ++j) { \
            const float inh = cm[j]*ih[0] + cm[3+j]*ih[1] + cm[6+j]*ih[2]; \
            const float arg = (dd[j] - inh) * INV3f; \
            float t; asm("tanh.approx.f32 %0, %1;" : "=f"(t) : "f"(arg)); \
            opt[(J) * (long)ROWF + j] = 3.0f * t; \
        } \
    } \
    dRr[0][J] = xb0; dRr[1][J] = xb1; dRr[2][J] = xb2; \
    sRr[0][J] = OMDf * s3[0]; \
    sRr[1][J] = OMDf * s3[1]; \
    sRr[2][J] = OMDf * s3[2]; }

#define CPWAIT(N) asm volatile("cp.async.wait_group " #N ";\n" ::: "memory")

// ONE barrier per batch; buf (SB+2)&3 was fully read two batches ago.
#define BB(SB, S0, EMIT, WN, ISS) { \
    CPWAIT(WN); __syncthreads(); \
    if (ISS) ISSUE(rb + 8, ((SB)+2)&3) \
    const float* bps = stage + (SB) * BUFF + 3 * tid; \
    ROWB((S0)+0, 0, EMIT) ROWB((S0)+1, 1, EMIT) \
    ROWB((S0)+2, 2, EMIT) ROWB((S0)+3, 3, EMIT) \
    rb += 4; if (EMIT) opt += 4 * (long)ROWF; }

    // prologue: batches 0,1 in flight
    ISSUE(rb,     0)
    ISSUE(rb + 4, 1)

    // warm-up: batches 0..7 (rows h0-30 .. h0+1)
    BB(0,0, 0,1,1) BB(1,4, 0,1,1) BB(2,0, 0,1,1) BB(3,4, 0,1,1)
    BB(0,0, 0,1,1) BB(1,4, 0,1,1) BB(2,0, 0,1,1) BB(3,4, 0,1,1)

    // emit: batches 8..67 (ro = h0 .. h0+239)
#pragma unroll 1
    for (int p = 0; p < 15; ++p) {
        BB(0,0, 1,1,1) BB(1,4, 1,1,1) BB(2,0, 1,1,1) BB(3,4, 1,1,1)
    }

    // k=68,69 (last ISSUE: batch 71), k=70, k=71 (ro up to h0+255)
    BB(0,0, 1,1,1) BB(1,4, 1,1,1) BB(2,0, 1,1,0) BB(3,4, 1,0,0)

#undef BB
#undef CPWAIT
#undef ROWB
#undef ISSUE
#undef CPA
}

extern "C" void kernel_launch(void* const* d_in, const int* in_sizes, int n_in,
                              void* d_out, int out_size)
{
    const float* D   = (const float*)d_in[0];   // (4096, 4096, 3) f32
    const float* Cm  = (const float*)d_in[1];   // (3, 3) f32
    float*       out = (float*)d_out;           // (4096, 4096, 3) f32
    dim3 grid(32, 16);                          // 512 blocks, 128-col strips
    chem_kernel<<<grid, TPB>>>(D, Cm, out);
}

// round 14
// speedup vs baseline: 1.8331x; 1.8331x over previous
#include <cuda_runtime.h>
typedef unsigned int u32;

#define HH 4096
#define ROWF 12288          // floats per image row
#define TPB 384             // one thread per (col, chan)
#define RS 408              // floats per staged row (128+8 halo cols)
#define BUFF 1632           // floats per 4-row stage buffer
#define BUFB 6528           // bytes per 4-row stage buffer

// horizontal taps: radius-1, renormalized to unit applied mass
#define KH0 0.78698593f
#define KH1 0.10650699f
// vertical taps: radius-2, reference-normalized
#define K0f 0.78657070f
#define K1f 0.10645078f
#define K2f 2.63866e-4f
#define DECAYf 0.60653065971263342f
#define OMDf   0.39346934028736658f
#define INV3f  0.33333322222f        // 1/(3 + 1e-6)

__global__ __launch_bounds__(TPB, 5)
void chem_kernel(const float* __restrict__ D, const float* __restrict__ Cm,
                 float* __restrict__ out)
{
    __shared__ float stage[4 * BUFF];    // 26112 B, 4-deep 4-row ring
    __shared__ float shI[2][4][TPB];     // 12288 B, batch-parity double buffer

    const int tid = threadIdx.x;
    const int c   = tid % 3;
    const int wb_ = tid - c;
    const int w0  = blockIdx.x << 7;     // 32 strips of 128 cols
    const int by  = blockIdx.y;          // 23 row chunks: 179,179,178*21
    const int h0  = 178 * by + (by < 2 ? by : 2);
    const int hend = h0 + (by < 2 ? 179 : 178);

    const float cc0 = __ldg(Cm + 0 + c);
    const float cc1 = __ldg(Cm + 3 + c);
    const float cc2 = __ldg(Cm + 6 + c);

    // cp.async loader: vec v of 408 -> (row v/102, lane v%102)
    const int  j0   = tid / 102, v0 = tid - 102 * j0;
    const int  g0   = (w0 - 4) * 3 + 4 * v0;           // row-relative float idx
    const bool cok0 = (g0 >= 0) && (g0 + 4 <= ROWF);
    const bool sec  = tid < 24;                        // vecs 384..407 (row 3)
    const int  g1   = (w0 - 4) * 3 + 4 * (78 + tid);
    const bool cok1 = sec && (g1 >= 0) && (g1 + 4 <= ROWF);

    const u32 sb  = (u32)__cvta_generic_to_shared(stage);
    const u32 sA0 = sb + (u32)((j0 * RS + 4 * v0) * 4);
    const u32 sA1 = sb + (u32)((3 * RS + 4 * (78 + tid)) * 4);

    float hb[8] = {0,0,0,0,0,0,0,0};   // horizontal-blur ring
    float dr[4] = {0,0,0,0};           // raw density ring (lag 2)
    float sr[4] = {0,0,0,0};           // soft-cloud ring (lag 2)
    float ds[4];                       // density stash (MIX consumes pre-refill)
    float siir = 0.f;

    int rb  = h0 - 26;                 // 52 batches of 4 rows; MIX from k=8
    int rom = h0;                      // MIX row base
    float* opm = out + (long)h0 * ROWF + w0 * 3 + tid;

#define ISSUE(RB, SBUF) { \
    const int  row = (RB) + j0; \
    const int  sz  = (cok0 && row >= 0 && row < HH) ? 16 : 0; \
    const float* gp = sz ? (D + (long)row * ROWF + g0) : D; \
    asm volatile("cp.async.cg.shared.global [%0], [%1], 16, %2;\n" \
                 :: "r"(sA0 + (u32)(SBUF) * BUFB), "l"(gp), "r"(sz) : "memory"); \
    if (sec) { \
        const int  row1 = (RB) + 3; \
        const int  sz1  = (cok1 && row1 >= 0 && row1 < HH) ? 16 : 0; \
        const float* gp1 = sz1 ? (D + (long)row1 * ROWF + g1) : D; \
        asm volatile("cp.async.cg.shared.global [%0], [%1], 16, %2;\n" \
                     :: "r"(sA1 + (u32)(SBUF) * BUFB), "l"(gp1), "r"(sz1) : "memory"); \
    } \
    asm volatile("cp.async.commit_group;\n" ::: "memory"); }

// Row at phase S; output row ro = r-2 (lag-2 rings). shI/ds always written;
// warm batches' values are simply never MIXed.
#define ROWE(S, J, PH) { \
    const float* bp = stgf + (J) * RS; \
    const float xm1 = bp[tid+9], x0 = bp[tid+12], xp1 = bp[tid+15]; \
    siir = fmaf(DECAYf, siir, x0); \
    hb[(S)&7] = fmaf(xm1 + xp1, KH1, x0 * KH0); \
    float vb_ = hb[((S)+6)&7] * K0f; \
    vb_ = fmaf(hb[((S)+5)&7] + hb[((S)+7)&7], K1f, vb_); \
    vb_ = fmaf(hb[((S)+4)&7] + hb[(S)&7],     K2f, vb_); \
    const float d_o = dr[((S)+2)&3]; \
    const float s_o = sr[((S)+2)&3]; \
    ds[J] = d_o; \
    shI[PH][J][tid] = s_o + (d_o * INV3f) * (vb_ - s_o); \
    dr[(S)&3] = x0; \
    sr[(S)&3] = OMDf * siir; }

#define MIX1(PB, J) { \
    if (rom + (J) < hend) { \
        const float i0 = shI[PB][J][wb_], i1 = shI[PB][J][wb_+1], i2 = shI[PB][J][wb_+2]; \
        const float inh = cc0*i0 + cc1*i1 + cc2*i2; \
        const float arg = (ds[J] - inh) * INV3f; \
        float t; asm("tanh.approx.f32 %0, %1;" : "=f"(t) : "f"(arg)); \
        __stcs(opm + (J) * (long)ROWF, 3.0f * t); \
    } }

#define MIXB(PB) { MIX1(PB,0) MIX1(PB,1) MIX1(PB,2) MIX1(PB,3) \
                   rom += 4; opm += 4 * (long)ROWF; }

#define CPWAIT(N) asm volatile("cp.async.wait_group " #N ";\n" ::: "memory")

// ONE barrier per batch; stage buf (SB+2)&3 was fully read 2 batches ago.
// MIX consumes ds[] of the previous batch BEFORE ROWE refills it.
#define BB(SB, S0, PH, DOMIX, DOISS, WN) { \
    CPWAIT(WN); __syncthreads(); \
    if (DOISS) ISSUE(rb + 8, ((SB)+2)&3) \
    if (DOMIX) { MIXB((PH)^1) } \
    const float* stgf = stage + (SB) * BUFF; \
    ROWE((S0)+0, 0, PH) ROWE((S0)+1, 1, PH) \
    ROWE((S0)+2, 2, PH) ROWE((S0)+3, 3, PH) \
    rb += 4; }

    // prologue: batches 0,1 in flight
    ISSUE(rb,     0)
    ISSUE(rb + 4, 1)

    // warm-up groups: batches 0..7 (commit rows h0-26 .. h0+5; MIX not started)
    BB(0,0,0, 0,1,1) BB(1,4,1, 0,1,1) BB(2,0,0, 0,1,1) BB(3,4,1, 0,1,1)
    BB(0,0,0, 0,1,1) BB(1,4,1, 0,1,1) BB(2,0,0, 0,1,1) BB(3,4,1, 0,1,1)

    // steady state: batches 8..47 (MIX batch k-1; rows h0.. )
#pragma unroll 1
    for (int p = 0; p < 10; ++p) {
        BB(0,0,0, 1,1,1) BB(1,4,1, 1,1,1) BB(2,0,0, 1,1,1) BB(3,4,1, 1,1,1)
    }

    // tail group: batches 48..51 (last ISSUE at batch 49 -> batch 51)
    BB(0,0,0, 1,1,1) BB(1,4,1, 1,1,1) BB(2,0,0, 1,0,1) BB(3,4,1, 1,0,0)

    // epilogue: MIX batch 51 (rows h0+176..h0+179, predicated by hend)
    __syncthreads();
    MIXB(1)

#undef BB
#undef CPWAIT
#undef MIXB
#undef MIX1
#undef ROWE
#undef ISSUE
}

extern "C" void kernel_launch(void* const* d_in, const int* in_sizes, int n_in,
                              void* d_out, int out_size)
{
    const float* D   = (const float*)d_in[0];   // (4096, 4096, 3) f32
    const float* Cm  = (const float*)d_in[1];   // (3, 3) f32
    float*       out = (float*)d_out;           // (4096, 4096, 3) f32
    dim3 grid(32, 23);                          // 736 blocks ~= 5/SM x 148 SMs
    chem_kernel<<<grid, TPB>>>(D, Cm, out);
}